// round 9
// baseline (speedup 1.0000x reference)
#include <cuda_runtime.h>
#include <cuda_fp16.h>
#include <cstdint>
#include <math.h>

// ---------------------------------------------------------------------------
// SelfAttention, legacy HMMA path, fp32-accurate fp16 hi/lo split
// (A@B = Ahi@Bhi + Ahi@Blo + Alo@Bhi, fp32 accumulate).
// 128-thread CTA, 4 warps (2Mx2N), warp tile 64x64 (128 acc regs ->
// 83 B/cyc LDS per HMMA-cyc, under the 128 B/cyc crossbar). 3-stage
// cp.async (96KB) -> 2 CTAs/SM for cross-CTA phase overlap.
//   GEMM1: qkv16 = hidden16 @ W16        (M=8192,N=3072,K=1024)  B=[K,N]
//   GEMM2: scores = Q16 @ K16^T * 1/32   (M=2048,N=2048,K=1024)  B=[N,K]
//   softmax -> P16 planes
//   GEMM3: out = P16 @ V16               (M=2048,N=1024,K=2048)  B=[K,N]
// ---------------------------------------------------------------------------

#define BATCH 4
#define SEQ   2048
#define EMB   1024
#define BS    8192

__device__ __half g_hidh[(long)BS * EMB];
__device__ __half g_hidl[(long)BS * EMB];
__device__ __half g_wh[(long)EMB * 3 * EMB];
__device__ __half g_wl[(long)EMB * 3 * EMB];
__device__ __half g_qkvh[(long)BS * 3 * EMB];
__device__ __half g_qkvl[(long)BS * 3 * EMB];
__device__ float  g_scores[(long)BATCH * SEQ * SEQ];
__device__ __half g_ph[(long)BATCH * SEQ * SEQ];
__device__ __half g_pl[(long)BATCH * SEQ * SEQ];

// ---------------- helpers ----------------
__device__ __forceinline__ uint32_t smem_u32(const void* p) {
    uint32_t a;
    asm("{ .reg .u64 t; cvta.to.shared.u64 t, %1; cvt.u32.u64 %0, t; }"
        : "=r"(a) : "l"(p));
    return a;
}

__device__ __forceinline__ void cp16(uint32_t d, const void* s) {
    asm volatile("cp.async.cg.shared.global [%0], [%1], 16;" :: "r"(d), "l"(s));
}

#define LDSM_X4(r, a)                                                        \
    asm volatile("ldmatrix.sync.aligned.m8n8.x4.shared.b16 {%0,%1,%2,%3}, [%4];" \
                 : "=r"((r)[0]), "=r"((r)[1]), "=r"((r)[2]), "=r"((r)[3])    \
                 : "r"(a))

#define LDSM_X4_T(r0, r1, r2, r3, a)                                         \
    asm volatile("ldmatrix.sync.aligned.m8n8.x4.trans.shared.b16 {%0,%1,%2,%3}, [%4];" \
                 : "=r"(r0), "=r"(r1), "=r"(r2), "=r"(r3)                    \
                 : "r"(a))

__device__ __forceinline__ void mma16816(float* c, const uint32_t* a, const uint32_t* b) {
    asm volatile(
        "mma.sync.aligned.m16n8k16.row.col.f32.f16.f16.f32 "
        "{%0,%1,%2,%3}, {%4,%5,%6,%7}, {%8,%9}, {%0,%1,%2,%3};"
        : "+f"(c[0]), "+f"(c[1]), "+f"(c[2]), "+f"(c[3])
        : "r"(a[0]), "r"(a[1]), "r"(a[2]), "r"(a[3]), "r"(b[0]), "r"(b[1]));
}

// ---------------- GEMM ----------------
// BM=BN=128, BK=32 halves. 128 threads = 4 warps (2M x 2N), warp tile 64x64.
// Smem atom-tiled: A plane = [m-oct][k-oct] 128B tiles; B(NK) plane likewise
// (n rows); B(KN) plane = [k-oct][n-oct] tiles. 8KB/plane; stage = 32KB.
#define APL 8192
#define STAGE 32768
#define NSTG 3
#define SMEM_GEMM (NSTG * STAGE)

template <int BNK, int OUTH>
__global__ __launch_bounds__(128)
void hmma_gemm(const __half* __restrict__ Ah, const __half* __restrict__ Al,
               int lda, long sA,
               const __half* __restrict__ Bh, const __half* __restrict__ Bl,
               int ldb, long sB,
               float* __restrict__ C, __half* __restrict__ Ch, __half* __restrict__ Cl,
               int ldc, long sC, int K, float alpha)
{
    extern __shared__ char sm[];
    const uint32_t sbase = smem_u32(sm);

    const int tid = threadIdx.x;
    const int lane = tid & 31;
    const int wid = tid >> 5;

    const int bz = blockIdx.z;
    Ah += (long)bz * sA;  Al += (long)bz * sA;
    Bh += (long)bz * sB;  Bl += (long)bz * sB;
    const int row0 = blockIdx.y * 128;
    const int col0 = blockIdx.x * 128;

    const int mb = (wid >> 1) * 64;   // warp M offset
    const int nb = (wid & 1) * 64;    // warp N offset

    // ---- fragment lane parts ----
    const int g = lane >> 3, fr = lane & 7;
    const uint32_t aLane = (uint32_t)((g & 1) * 512 + (g >> 1) * 128 + fr * 16);
    const uint32_t aWarp = (uint32_t)((mb >> 3) * 512);
    const uint32_t btLane = (uint32_t)((g & 1) * 2048 + (g >> 1) * 128 + fr * 16 + (nb >> 3) * 128);
    const uint32_t bnLane = (uint32_t)((g >> 1) * 512 + (g & 1) * 128 + fr * 16 + (nb >> 3) * 512);

    float acc[4][8][4];
    #pragma unroll
    for (int i = 0; i < 4; i++)
        #pragma unroll
        for (int j = 0; j < 8; j++)
            #pragma unroll
            for (int e = 0; e < 4; e++) acc[i][j][e] = 0.0f;

    const int nIter = K / 32;

    auto issue = [&](int kb) {
        const uint32_t st = sbase + (uint32_t)(kb % NSTG) * STAGE;
        const int k0 = kb * 32;
        // A hi/lo: 512 atoms-rows per plane, 4 per thread
        #pragma unroll
        for (int it = 0; it < 4; it++) {
            const int idx = it * 128 + tid;
            const int aR = idx >> 2, aKo = idx & 3;
            const uint32_t aDst = (uint32_t)((((aR >> 3) * 4) + aKo) * 128 + (aR & 7) * 16);
            cp16(st + aDst, Ah + (long)(row0 + aR) * lda + k0 + aKo * 8);
            cp16(st + APL + aDst, Al + (long)(row0 + aR) * lda + k0 + aKo * 8);
        }
        if (BNK) {   // B [N,K]: A-style tiles
            #pragma unroll
            for (int it = 0; it < 4; it++) {
                const int idx = it * 128 + tid;
                const int aR = idx >> 2, aKo = idx & 3;
                const uint32_t aDst = (uint32_t)((((aR >> 3) * 4) + aKo) * 128 + (aR & 7) * 16);
                cp16(st + 2 * APL + aDst, Bh + (long)(col0 + aR) * ldb + k0 + aKo * 8);
                cp16(st + 3 * APL + aDst, Bl + (long)(col0 + aR) * ldb + k0 + aKo * 8);
            }
        } else {     // B [K,N]: [k-oct][n-oct] tiles
            #pragma unroll
            for (int it = 0; it < 4; it++) {
                const int idx = it * 128 + tid;
                const int bK = idx >> 4, bNo = idx & 15;
                const uint32_t btDst = (uint32_t)((((bK >> 3) * 16) + bNo) * 128 + (bK & 7) * 16);
                cp16(st + 2 * APL + btDst, Bh + (long)(k0 + bK) * ldb + col0 + bNo * 8);
                cp16(st + 3 * APL + btDst, Bl + (long)(k0 + bK) * ldb + col0 + bNo * 8);
            }
        }
        asm volatile("cp.async.commit_group;" ::: "memory");
    };

    issue(0);
    issue(1);

    for (int kb = 0; kb < nIter; kb++) {
        asm volatile("cp.async.wait_group 1;" ::: "memory");
        __syncthreads();

        if (kb + 2 < nIter) issue(kb + 2);
        else asm volatile("cp.async.commit_group;" ::: "memory");

        const uint32_t st = sbase + (uint32_t)(kb % NSTG) * STAGE;
        const uint32_t bBase = st + 2 * APL;
        #pragma unroll
        for (int ks = 0; ks < 2; ks++) {
            uint32_t bh[8][2], bl[8][2];
            #pragma unroll
            for (int j2 = 0; j2 < 4; j2++) {
                if (BNK) {
                    uint32_t bd = bBase + bnLane + (uint32_t)(j2 * 1024 + ks * 256);
                    LDSM_X4(bh[2 * j2], bd);
                    LDSM_X4(bl[2 * j2], bd + APL);
                } else {
                    uint32_t bd = bBase + btLane + (uint32_t)(ks * 4096 + j2 * 256);
                    LDSM_X4_T(bh[2 * j2][0], bh[2 * j2][1], bh[2 * j2 + 1][0], bh[2 * j2 + 1][1], bd);
                    LDSM_X4_T(bl[2 * j2][0], bl[2 * j2][1], bl[2 * j2 + 1][0], bl[2 * j2 + 1][1],
                              bd + APL);
                }
            }
            #pragma unroll
            for (int i = 0; i < 4; i++) {
                uint32_t ah[4], al[4];
                uint32_t ad = st + aWarp + aLane + (uint32_t)(i * 1024 + ks * 256);
                LDSM_X4(ah, ad);
                LDSM_X4(al, ad + APL);
                #pragma unroll
                for (int j = 0; j < 8; j++) mma16816(acc[i][j], ah, bh[j]);
                #pragma unroll
                for (int j = 0; j < 8; j++) mma16816(acc[i][j], ah, bl[j]);
                #pragma unroll
                for (int j = 0; j < 8; j++) mma16816(acc[i][j], al, bh[j]);
            }
        }
        __syncthreads();
    }

    // ---- epilogue ----
    #pragma unroll
    for (int i = 0; i < 4; i++) {
        const int r = row0 + mb + i * 16 + (lane >> 2);
        #pragma unroll
        for (int j = 0; j < 8; j++) {
            const int c = col0 + nb + j * 8 + (lane & 3) * 2;
            float v0 = acc[i][j][0] * alpha, v1 = acc[i][j][1] * alpha;
            float v2 = acc[i][j][2] * alpha, v3 = acc[i][j][3] * alpha;
            if (OUTH) {
                __half h0 = __float2half_rn(v0), h1 = __float2half_rn(v1);
                __half h2 = __float2half_rn(v2), h3 = __float2half_rn(v3);
                __half l0 = __float2half_rn(v0 - __half2float(h0));
                __half l1 = __float2half_rn(v1 - __half2float(h1));
                __half l2 = __float2half_rn(v2 - __half2float(h2));
                __half l3 = __float2half_rn(v3 - __half2float(h3));
                __half* chp = Ch + (long)bz * sC;
                __half* clp = Cl + (long)bz * sC;
                *reinterpret_cast<__half2*>(chp + (long)r * ldc + c) = __halves2half2(h0, h1);
                *reinterpret_cast<__half2*>(chp + (long)(r + 8) * ldc + c) = __halves2half2(h2, h3);
                *reinterpret_cast<__half2*>(clp + (long)r * ldc + c) = __halves2half2(l0, l1);
                *reinterpret_cast<__half2*>(clp + (long)(r + 8) * ldc + c) = __halves2half2(l2, l3);
            } else {
                float* cp = C + (long)bz * sC;
                *reinterpret_cast<float2*>(cp + (long)r * ldc + c) = make_float2(v0, v1);
                *reinterpret_cast<float2*>(cp + (long)(r + 8) * ldc + c) = make_float2(v2, v3);
            }
        }
    }
}

// ---------------- fp32 -> fp16 hi/lo split convert ----------------
__global__ __launch_bounds__(256)
void cvt_split(const float4* __restrict__ src, __half2* __restrict__ dh,
               __half2* __restrict__ dl, long n4)
{
    long i = blockIdx.x * 256L + threadIdx.x;
    long stride = (long)gridDim.x * 256;
    for (; i < n4; i += stride) {
        float4 v = src[i];
        __half h0 = __float2half_rn(v.x), h1 = __float2half_rn(v.y);
        __half h2 = __float2half_rn(v.z), h3 = __float2half_rn(v.w);
        dh[2 * i]     = __halves2half2(h0, h1);
        dh[2 * i + 1] = __halves2half2(h2, h3);
        dl[2 * i]     = __halves2half2(__float2half_rn(v.x - __half2float(h0)),
                                       __float2half_rn(v.y - __half2float(h1)));
        dl[2 * i + 1] = __halves2half2(__float2half_rn(v.z - __half2float(h2)),
                                       __float2half_rn(v.w - __half2float(h3)));
    }
}

// ---------------- softmax: fp32 scores row -> fp16 hi/lo P planes ----------
__global__ __launch_bounds__(256)
void softmax_kernel(const float* __restrict__ scores,
                    __half2* __restrict__ ph, __half2* __restrict__ pl)
{
    __shared__ float red[8];
    const long row = blockIdx.x;
    const float4* r4 = reinterpret_cast<const float4*>(scores + row * (long)SEQ);
    const int tid = threadIdx.x;
    const int wid = tid >> 5, lane = tid & 31;

    float4 a = r4[tid];
    float4 b = r4[tid + 256];

    float m = fmaxf(fmaxf(fmaxf(a.x, a.y), fmaxf(a.z, a.w)),
                    fmaxf(fmaxf(b.x, b.y), fmaxf(b.z, b.w)));
    #pragma unroll
    for (int o = 16; o; o >>= 1) m = fmaxf(m, __shfl_xor_sync(0xffffffffu, m, o));
    if (lane == 0) red[wid] = m;
    __syncthreads();
    float rowmax = red[0];
    #pragma unroll
    for (int i = 1; i < 8; i++) rowmax = fmaxf(rowmax, red[i]);
    __syncthreads();

    a.x = __expf(a.x - rowmax); a.y = __expf(a.y - rowmax);
    a.z = __expf(a.z - rowmax); a.w = __expf(a.w - rowmax);
    b.x = __expf(b.x - rowmax); b.y = __expf(b.y - rowmax);
    b.z = __expf(b.z - rowmax); b.w = __expf(b.w - rowmax);

    float s = a.x + a.y + a.z + a.w + b.x + b.y + b.z + b.w;
    #pragma unroll
    for (int o = 16; o; o >>= 1) s += __shfl_xor_sync(0xffffffffu, s, o);
    if (lane == 0) red[wid] = s;
    __syncthreads();
    float tot = red[0];
    #pragma unroll
    for (int i = 1; i < 8; i++) tot += red[i];
    const float inv = 1.0f / tot;

    a.x *= inv; a.y *= inv; a.z *= inv; a.w *= inv;
    b.x *= inv; b.y *= inv; b.z *= inv; b.w *= inv;

    __half2* phr = ph + row * (SEQ / 2);
    __half2* plr = pl + row * (SEQ / 2);
    auto emit = [&](int idx2, float x, float y) {
        __half hx = __float2half_rn(x), hy = __float2half_rn(y);
        phr[idx2] = __halves2half2(hx, hy);
        plr[idx2] = __halves2half2(__float2half_rn(x - __half2float(hx)),
                                   __float2half_rn(y - __half2float(hy)));
    };
    emit(2 * tid, a.x, a.y);
    emit(2 * tid + 1, a.z, a.w);
    emit(2 * (tid + 256), b.x, b.y);
    emit(2 * (tid + 256) + 1, b.z, b.w);
}

// ---------------- launch ----------------
extern "C" void kernel_launch(void* const* d_in, const int* in_sizes, int n_in,
                              void* d_out, int out_size)
{
    const float* hidden = (const float*)d_in[0];
    const float* W      = (const float*)d_in[1];
    float* out          = (float*)d_out;

    __half *hidh, *hidl, *wh, *wl, *qkvh, *qkvl, *ph, *pl;
    float *scores;
    cudaGetSymbolAddress((void**)&hidh, g_hidh);
    cudaGetSymbolAddress((void**)&hidl, g_hidl);
    cudaGetSymbolAddress((void**)&wh, g_wh);
    cudaGetSymbolAddress((void**)&wl, g_wl);
    cudaGetSymbolAddress((void**)&qkvh, g_qkvh);
    cudaGetSymbolAddress((void**)&qkvl, g_qkvl);
    cudaGetSymbolAddress((void**)&scores, g_scores);
    cudaGetSymbolAddress((void**)&ph, g_ph);
    cudaGetSymbolAddress((void**)&pl, g_pl);

    cudaFuncSetAttribute(hmma_gemm<0, 1>, cudaFuncAttributeMaxDynamicSharedMemorySize, SMEM_GEMM);
    cudaFuncSetAttribute(hmma_gemm<1, 0>, cudaFuncAttributeMaxDynamicSharedMemorySize, SMEM_GEMM);
    cudaFuncSetAttribute(hmma_gemm<0, 0>, cudaFuncAttributeMaxDynamicSharedMemorySize, SMEM_GEMM);

    // split inputs
    cvt_split<<<1024, 256>>>((const float4*)hidden, (__half2*)hidh, (__half2*)hidl,
                             (long)BS * EMB / 4);
    cvt_split<<<1024, 256>>>((const float4*)W, (__half2*)wh, (__half2*)wl,
                             (long)EMB * 3 * EMB / 4);

    // GEMM1: qkv16 = hidden16 @ W16   (B=[K,N], out=halves)
    hmma_gemm<0, 1><<<dim3(3 * EMB / 128, BS / 128, 1), 128, SMEM_GEMM>>>(
        hidh, hidl, EMB, 0,
        wh, wl, 3 * EMB, 0,
        nullptr, qkvh, qkvl, 3 * EMB, 0,
        EMB, 1.0f);

    // GEMM2: scores = Q16 @ K16^T * 1/32   (B=[N,K] = K-section rows)
    hmma_gemm<1, 0><<<dim3(SEQ / 128, SEQ / 128, BATCH), 128, SMEM_GEMM>>>(
        qkvh, qkvl, 3 * EMB, (long)SEQ * 3 * EMB,
        qkvh + EMB, qkvl + EMB, 3 * EMB, (long)SEQ * 3 * EMB,
        scores, nullptr, nullptr, SEQ, (long)SEQ * SEQ,
        EMB, 1.0f / 32.0f);

    // softmax -> P16 planes
    softmax_kernel<<<BATCH * SEQ, 256>>>(scores, (__half2*)ph, (__half2*)pl);

    // GEMM3: out = P16 @ V16   (B=[K,N] = V rows)
    hmma_gemm<0, 0><<<dim3(EMB / 128, SEQ / 128, BATCH), 128, SMEM_GEMM>>>(
        ph, pl, SEQ, (long)SEQ * SEQ,
        qkvh + 2 * EMB, qkvl + 2 * EMB, 3 * EMB, (long)SEQ * 3 * EMB,
        out, nullptr, nullptr, EMB, (long)SEQ * EMB,
        SEQ, 1.0f);
}

// round 10
// speedup vs baseline: 1.5158x; 1.5158x over previous
#include <cuda_runtime.h>
#include <cuda_fp16.h>
#include <cstdint>
#include <math.h>

// ---------------------------------------------------------------------------
// SelfAttention via legacy tensor path (mma.sync HMMA, fp32-accurate fp16
// hi/lo split: A@B = Ahi@Bhi + Ahi@Blo + Alo@Bhi, fp32 accumulate):
//   qkv = hidden @ W                      (M=8192, N=3072, K=1024)  B=[K,N]
//   scores[b] = Q[b] @ K[b]^T * 1/32      (M=2048, N=2048, K=1024)  B=[N,K]
//   P = softmax_rows(scores)
//   out[b] = P[b] @ V[b]                  (M=2048, N=1024, K=2048)  B=[K,N]
//     (GEMM3 uses 2-term split: Ph@Vh + Ph@Vl; P in [0,1] -> err ~1e-4)
// R3 (1079us) structure, plus direct [N,K] B path (no transpose kernel).
// ---------------------------------------------------------------------------

#define BATCH 4
#define SEQ   2048
#define EMB   1024
#define BS    8192

__device__ float g_qkv[(long)BS * 3 * EMB];          // [8192, 3072]
__device__ float g_scores[(long)BATCH * SEQ * SEQ];  // [4, 2048, 2048]

// ---------------- helpers ----------------
__device__ __forceinline__ uint32_t smem_u32(const void* p) {
    uint32_t a;
    asm("{ .reg .u64 t; cvta.to.shared.u64 t, %1; cvt.u32.u64 %0, t; }"
        : "=r"(a) : "l"(p));
    return a;
}

#define LDSM_X4(r, a)                                                        \
    asm volatile("ldmatrix.sync.aligned.m8n8.x4.shared.b16 {%0,%1,%2,%3}, [%4];" \
                 : "=r"((r)[0]), "=r"((r)[1]), "=r"((r)[2]), "=r"((r)[3])    \
                 : "r"(a))

#define LDSM_X4_T(r0, r1, r2, r3, a)                                         \
    asm volatile("ldmatrix.sync.aligned.m8n8.x4.trans.shared.b16 {%0,%1,%2,%3}, [%4];" \
                 : "=r"(r0), "=r"(r1), "=r"(r2), "=r"(r3)                    \
                 : "r"(a))

__device__ __forceinline__ void mma16816(float* c, const uint32_t* a, const uint32_t* b) {
    asm volatile(
        "mma.sync.aligned.m16n8k16.row.col.f32.f16.f16.f32 "
        "{%0,%1,%2,%3}, {%4,%5,%6,%7}, {%8,%9}, {%0,%1,%2,%3};"
        : "+f"(c[0]), "+f"(c[1]), "+f"(c[2]), "+f"(c[3])
        : "r"(a[0]), "r"(a[1]), "r"(a[2]), "r"(a[3]), "r"(b[0]), "r"(b[1]));
}

// split fp32x4 -> hi/lo fp16x4 packed as 2x b32 each
__device__ __forceinline__ void split4(float4 v, uint32_t* h, uint32_t* l) {
    __half h0 = __float2half_rn(v.x), h1 = __float2half_rn(v.y);
    __half h2 = __float2half_rn(v.z), h3 = __float2half_rn(v.w);
    __half l0 = __float2half_rn(v.x - __half2float(h0));
    __half l1 = __float2half_rn(v.y - __half2float(h1));
    __half l2 = __float2half_rn(v.z - __half2float(h2));
    __half l3 = __float2half_rn(v.w - __half2float(h3));
    __half2 ha = __halves2half2(h0, h1), hb = __halves2half2(h2, h3);
    __half2 la = __halves2half2(l0, l1), lb = __halves2half2(l2, l3);
    h[0] = *(uint32_t*)&ha; h[1] = *(uint32_t*)&hb;
    l[0] = *(uint32_t*)&la; l[1] = *(uint32_t*)&lb;
}

__device__ __forceinline__ void hi4(float4 v, uint32_t* h) {
    __half2 ha = __halves2half2(__float2half_rn(v.x), __float2half_rn(v.y));
    __half2 hb = __halves2half2(__float2half_rn(v.z), __float2half_rn(v.w));
    h[0] = *(uint32_t*)&ha; h[1] = *(uint32_t*)&hb;
}

__device__ __forceinline__ void sts64(uint32_t addr, uint32_t a, uint32_t b) {
    asm volatile("st.shared.v2.b32 [%0], {%1,%2};" :: "r"(addr), "r"(a), "r"(b));
}

// ---------------- GEMM ----------------
// Tile: BM=128, BN=128, BK=32 halves. 256 threads = 8 warps (2 M x 4 N),
// each warp 64x32 via 4x4 m16n8k16 tiles, fp16 hi/lo split.
// BNK=0: B gmem [K,N] row-major -> smem [k-row][n] 272B stride, trans-ldmatrix.
// BNK=1: B gmem [N,K] row-major -> smem [n-row][k] 80B stride, ldmatrix.
// NOLOA=1: drop the Alo@Bhi term (A already non-negative small range, e.g. P).
#define LDA_B   80                   // A smem row stride bytes (32h + 8h pad)
#define LDB_B   272                  // B smem row stride bytes (128h + 8h pad)
#define A_PLANE 10240                // 128 * 80
#define BT_PLANE 8704                // 32 * 272

template <int BNK, int NOLOA>
__global__ __launch_bounds__(256, 1)
void hmma_gemm(const float* __restrict__ A, int lda, long sA,
               const float* __restrict__ B, int ldb, long sB,
               float* __restrict__ C, int ldc, long sC,
               int K, float alpha)
{
    constexpr int BPLANE = BNK ? A_PLANE : BT_PLANE;
    constexpr int STAGE  = 2 * A_PLANE + 2 * BPLANE;

    extern __shared__ char sm[];
    const uint32_t sbase = smem_u32(sm);

    const int tid = threadIdx.x;
    const int lane = tid & 31;
    const int wid = tid >> 5;

    const int bz = blockIdx.z;
    A += (long)bz * sA;
    B += (long)bz * sB;
    C += (long)bz * sC;
    const int row0 = blockIdx.y * 128;
    const int col0 = blockIdx.x * 128;

    const int mb = (wid >> 2) * 64;   // warp M offset in tile
    const int nb = (wid & 3) * 32;    // warp N offset in tile

    // loader per-thread indices
    const int aR = tid >> 3;               // + j*32
    const int aC = (tid & 7) << 2;         // 0..28
    const int bK = tid >> 5;               // + j*8   (BNK=0)
    const int bN = (tid & 31) << 2;        // 0..124  (BNK=0)

    // fragment base addresses (per-lane)
    const uint32_t aFrag = sbase + (uint32_t)((mb + (lane & 15)) * LDA_B + (lane >> 4) * 16);
    const uint32_t bFrag = BNK
        ? sbase + 2 * A_PLANE +
          (uint32_t)((nb + (lane & 7) + ((lane >> 4) & 1) * 8) * LDA_B + ((lane >> 3) & 1) * 16)
        : sbase + 2 * A_PLANE +
          (uint32_t)(((lane & 7) + ((lane >> 3) & 1) * 8) * LDB_B + (nb + (lane >> 4) * 8) * 2);

    float acc[4][4][4];
    #pragma unroll
    for (int i = 0; i < 4; i++)
        #pragma unroll
        for (int j = 0; j < 4; j++)
            #pragma unroll
            for (int e = 0; e < 4; e++) acc[i][j][e] = 0.0f;

    const int nIter = K / 32;
    float4 aReg[4], bReg[4];

    // gmem loads for chunk k0
    auto ldg = [&](int k0) {
        #pragma unroll
        for (int j = 0; j < 4; j++)
            aReg[j] = *reinterpret_cast<const float4*>(
                A + (long)(row0 + j * 32 + aR) * lda + k0 + aC);
        if (BNK) {
            #pragma unroll
            for (int j = 0; j < 4; j++)
                bReg[j] = *reinterpret_cast<const float4*>(
                    B + (long)(col0 + j * 32 + aR) * ldb + k0 + aC);
        } else {
            #pragma unroll
            for (int j = 0; j < 4; j++)
                bReg[j] = *reinterpret_cast<const float4*>(
                    B + (long)(k0 + j * 8 + bK) * ldb + col0 + bN);
        }
    };
    // convert + store staged regs into stage st
    auto sts = [&](uint32_t st) {
        #pragma unroll
        for (int j = 0; j < 4; j++) {
            uint32_t ad = sbase + st + (uint32_t)((j * 32 + aR) * LDA_B + aC * 2);
            if (NOLOA) {
                uint32_t h[2];
                hi4(aReg[j], h);
                sts64(ad, h[0], h[1]);
            } else {
                uint32_t h[2], l[2];
                split4(aReg[j], h, l);
                sts64(ad, h[0], h[1]);
                sts64(ad + A_PLANE, l[0], l[1]);
            }
        }
        #pragma unroll
        for (int j = 0; j < 4; j++) {
            uint32_t h[2], l[2];
            split4(bReg[j], h, l);
            uint32_t ad;
            if (BNK)
                ad = sbase + st + 2 * A_PLANE + (uint32_t)((j * 32 + aR) * LDA_B + aC * 2);
            else
                ad = sbase + st + 2 * A_PLANE + (uint32_t)((j * 8 + bK) * LDB_B + bN * 2);
            sts64(ad, h[0], h[1]);
            sts64(ad + BPLANE, l[0], l[1]);
        }
    };

    ldg(0);
    sts(0);
    __syncthreads();

    for (int kb = 0; kb < nIter; kb++) {
        if (kb + 1 < nIter) ldg((kb + 1) * 32);   // prefetch next chunk

        const uint32_t st = (uint32_t)(kb & 1) * STAGE;
        #pragma unroll
        for (int ks = 0; ks < 2; ks++) {
            uint32_t ah[4][4], al[4][4], bh[4][2], bl[4][2];
            #pragma unroll
            for (int i = 0; i < 4; i++) {
                uint32_t ad = aFrag + st + (uint32_t)(i * 16 * LDA_B + ks * 32);
                LDSM_X4(ah[i], ad);
                if (!NOLOA) LDSM_X4(al[i], ad + A_PLANE);
            }
            #pragma unroll
            for (int j2 = 0; j2 < 2; j2++) {
                if (BNK) {
                    uint32_t bd = bFrag + st + (uint32_t)(j2 * 16 * LDA_B + ks * 32);
                    LDSM_X4(bh[2 * j2], bd);
                    LDSM_X4(bl[2 * j2], bd + BPLANE);
                } else {
                    uint32_t bd = bFrag + st + (uint32_t)(ks * 16 * LDB_B + j2 * 32);
                    LDSM_X4_T(bh[2 * j2][0], bh[2 * j2][1], bh[2 * j2 + 1][0], bh[2 * j2 + 1][1], bd);
                    LDSM_X4_T(bl[2 * j2][0], bl[2 * j2][1], bl[2 * j2 + 1][0], bl[2 * j2 + 1][1],
                              bd + BPLANE);
                }
            }
            #pragma unroll
            for (int i = 0; i < 4; i++)
                #pragma unroll
                for (int j = 0; j < 4; j++) mma16816(acc[i][j], ah[i], bh[j]);
            #pragma unroll
            for (int i = 0; i < 4; i++)
                #pragma unroll
                for (int j = 0; j < 4; j++) mma16816(acc[i][j], ah[i], bl[j]);
            if (!NOLOA) {
                #pragma unroll
                for (int i = 0; i < 4; i++)
                    #pragma unroll
                    for (int j = 0; j < 4; j++) mma16816(acc[i][j], al[i], bh[j]);
            }
        }

        if (kb + 1 < nIter) sts((uint32_t)((kb + 1) & 1) * STAGE);
        __syncthreads();
    }

    // epilogue
    #pragma unroll
    for (int i = 0; i < 4; i++) {
        const int r = row0 + mb + i * 16 + (lane >> 2);
        #pragma unroll
        for (int j = 0; j < 4; j++) {
            const int c = col0 + nb + j * 8 + (lane & 3) * 2;
            float2 v0 = make_float2(acc[i][j][0] * alpha, acc[i][j][1] * alpha);
            float2 v1 = make_float2(acc[i][j][2] * alpha, acc[i][j][3] * alpha);
            *reinterpret_cast<float2*>(C + (long)r * ldc + c) = v0;
            *reinterpret_cast<float2*>(C + (long)(r + 8) * ldc + c) = v1;
        }
    }
}

// ---------------- softmax: one row (2048) per 256-thread block ----------------
__global__ __launch_bounds__(256)
void softmax_kernel(float* __restrict__ scores)
{
    __shared__ float red[8];
    const long row = blockIdx.x;
    float4* r4 = reinterpret_cast<float4*>(scores + row * (long)SEQ);
    const int tid = threadIdx.x;
    const int wid = tid >> 5, lane = tid & 31;

    float4 a = r4[tid];
    float4 b = r4[tid + 256];

    float m = fmaxf(fmaxf(fmaxf(a.x, a.y), fmaxf(a.z, a.w)),
                    fmaxf(fmaxf(b.x, b.y), fmaxf(b.z, b.w)));
    #pragma unroll
    for (int o = 16; o; o >>= 1) m = fmaxf(m, __shfl_xor_sync(0xffffffffu, m, o));
    if (lane == 0) red[wid] = m;
    __syncthreads();
    float rowmax = red[0];
    #pragma unroll
    for (int i = 1; i < 8; i++) rowmax = fmaxf(rowmax, red[i]);
    __syncthreads();

    a.x = __expf(a.x - rowmax); a.y = __expf(a.y - rowmax);
    a.z = __expf(a.z - rowmax); a.w = __expf(a.w - rowmax);
    b.x = __expf(b.x - rowmax); b.y = __expf(b.y - rowmax);
    b.z = __expf(b.z - rowmax); b.w = __expf(b.w - rowmax);

    float s = a.x + a.y + a.z + a.w + b.x + b.y + b.z + b.w;
    #pragma unroll
    for (int o = 16; o; o >>= 1) s += __shfl_xor_sync(0xffffffffu, s, o);
    if (lane == 0) red[wid] = s;
    __syncthreads();
    float tot = red[0];
    #pragma unroll
    for (int i = 1; i < 8; i++) tot += red[i];
    const float inv = 1.0f / tot;

    a.x *= inv; a.y *= inv; a.z *= inv; a.w *= inv;
    b.x *= inv; b.y *= inv; b.z *= inv; b.w *= inv;
    r4[tid] = a;
    r4[tid + 256] = b;
}

// ---------------- launch ----------------
extern "C" void kernel_launch(void* const* d_in, const int* in_sizes, int n_in,
                              void* d_out, int out_size)
{
    const float* hidden = (const float*)d_in[0];   // [4,2048,1024]
    const float* W      = (const float*)d_in[1];   // [1024,3072]
    float* out          = (float*)d_out;           // [4,2048,1024]

    float* qkv = nullptr; float* scores = nullptr;
    cudaGetSymbolAddress((void**)&qkv, g_qkv);
    cudaGetSymbolAddress((void**)&scores, g_scores);

    constexpr int SM_BT = 2 * (2 * A_PLANE + 2 * BT_PLANE);  // 75776
    constexpr int SM_BN = 2 * (4 * A_PLANE);                 // 81920
    cudaFuncSetAttribute(hmma_gemm<0, 0>, cudaFuncAttributeMaxDynamicSharedMemorySize, SM_BT);
    cudaFuncSetAttribute(hmma_gemm<1, 0>, cudaFuncAttributeMaxDynamicSharedMemorySize, SM_BN);
    cudaFuncSetAttribute(hmma_gemm<0, 1>, cudaFuncAttributeMaxDynamicSharedMemorySize, SM_BT);

    // 1) qkv = hidden @ W   (M=8192, N=3072, K=1024), B=[K,N]
    hmma_gemm<0, 0><<<dim3(3 * EMB / 128, BS / 128, 1), 256, SM_BT>>>(
        hidden, EMB, 0,
        W, 3 * EMB, 0,
        qkv, 3 * EMB, 0,
        EMB, 1.0f);

    // 2) scores[b] = Q[b] @ K[b]^T * 1/32   (B = K-section rows, [N,K])
    hmma_gemm<1, 0><<<dim3(SEQ / 128, SEQ / 128, BATCH), 256, SM_BN>>>(
        qkv, 3 * EMB, (long)SEQ * 3 * EMB,
        qkv + EMB, 3 * EMB, (long)SEQ * 3 * EMB,
        scores, SEQ, (long)SEQ * SEQ,
        EMB, 1.0f / 32.0f);

    // 3) softmax rows (in place)
    softmax_kernel<<<BATCH * SEQ, 256>>>(scores);

    // 4) out[b] = P[b] @ V[b]   (M=2048, N=1024, K=2048), B=[K,N], 2-term P
    hmma_gemm<0, 1><<<dim3(EMB / 128, SEQ / 128, BATCH), 256, SM_BT>>>(
        scores, SEQ, (long)SEQ * SEQ,
        qkv + 2 * EMB, 3 * EMB, (long)SEQ * 3 * EMB,
        out, EMB, (long)SEQ * EMB,
        SEQ, 1.0f);
}

// round 13
// speedup vs baseline: 1.5276x; 1.0078x over previous
#include <cuda_runtime.h>
#include <cuda_fp16.h>
#include <cstdint>
#include <math.h>

// ---------------------------------------------------------------------------
// SelfAttention via legacy tensor path (mma.sync HMMA, fp32-accurate fp16
// hi/lo split: A@B = Ahi@Bhi + Ahi@Blo + Alo@Bhi, fp32 accumulate):
//   qkv = hidden @ W                      (M=8192, N=3072, K=1024)  B=[K,N]
//   scores[b] = Q[b] @ K[b]^T * 1/32      (M=2048, N=2048, K=1024)  B=[N,K]
//   P = softmax_rows(scores)
//   out[b] = P[b] @ V[b]                  (M=2048, N=1024, K=2048)  B=[K,N]
//     (GEMM3 2-term split: Ph@Vh + Ph@Vl; P in [0,1])
// R8 (968us) structure with BK=64 chunks (half the syncs/transitions).
// ---------------------------------------------------------------------------

#define BATCH 4
#define SEQ   2048
#define EMB   1024
#define BS    8192

__device__ float g_qkv[(long)BS * 3 * EMB];          // [8192, 3072]
__device__ float g_scores[(long)BATCH * SEQ * SEQ];  // [4, 2048, 2048]

// ---------------- helpers ----------------
__device__ __forceinline__ uint32_t smem_u32(const void* p) {
    uint32_t a;
    asm("{ .reg .u64 t; cvta.to.shared.u64 t, %1; cvt.u32.u64 %0, t; }"
        : "=r"(a) : "l"(p));
    return a;
}

#define LDSM_X4(r, a)                                                        \
    asm volatile("ldmatrix.sync.aligned.m8n8.x4.shared.b16 {%0,%1,%2,%3}, [%4];" \
                 : "=r"((r)[0]), "=r"((r)[1]), "=r"((r)[2]), "=r"((r)[3])    \
                 : "r"(a))

#define LDSM_X4_T(r0, r1, r2, r3, a)                                         \
    asm volatile("ldmatrix.sync.aligned.m8n8.x4.trans.shared.b16 {%0,%1,%2,%3}, [%4];" \
                 : "=r"(r0), "=r"(r1), "=r"(r2), "=r"(r3)                    \
                 : "r"(a))

__device__ __forceinline__ void mma16816(float* c, const uint32_t* a, const uint32_t* b) {
    asm volatile(
        "mma.sync.aligned.m16n8k16.row.col.f32.f16.f16.f32 "
        "{%0,%1,%2,%3}, {%4,%5,%6,%7}, {%8,%9}, {%0,%1,%2,%3};"
        : "+f"(c[0]), "+f"(c[1]), "+f"(c[2]), "+f"(c[3])
        : "r"(a[0]), "r"(a[1]), "r"(a[2]), "r"(a[3]), "r"(b[0]), "r"(b[1]));
}

// split fp32x4 -> hi/lo fp16x4 packed as 2x b32 each
__device__ __forceinline__ void split4(float4 v, uint32_t* h, uint32_t* l) {
    __half h0 = __float2half_rn(v.x), h1 = __float2half_rn(v.y);
    __half h2 = __float2half_rn(v.z), h3 = __float2half_rn(v.w);
    __half l0 = __float2half_rn(v.x - __half2float(h0));
    __half l1 = __float2half_rn(v.y - __half2float(h1));
    __half l2 = __float2half_rn(v.z - __half2float(h2));
    __half l3 = __float2half_rn(v.w - __half2float(h3));
    __half2 ha = __halves2half2(h0, h1), hb = __halves2half2(h2, h3);
    __half2 la = __halves2half2(l0, l1), lb = __halves2half2(l2, l3);
    h[0] = *(uint32_t*)&ha; h[1] = *(uint32_t*)&hb;
    l[0] = *(uint32_t*)&la; l[1] = *(uint32_t*)&lb;
}

__device__ __forceinline__ void hi4(float4 v, uint32_t* h) {
    __half2 ha = __halves2half2(__float2half_rn(v.x), __float2half_rn(v.y));
    __half2 hb = __halves2half2(__float2half_rn(v.z), __float2half_rn(v.w));
    h[0] = *(uint32_t*)&ha; h[1] = *(uint32_t*)&hb;
}

__device__ __forceinline__ void sts64(uint32_t addr, uint32_t a, uint32_t b) {
    asm volatile("st.shared.v2.b32 [%0], {%1,%2};" :: "r"(addr), "r"(a), "r"(b));
}

// ---------------- GEMM ----------------
// Tile: BM=128, BN=128, BK=64 halves. 256 threads = 8 warps (2M x 4N),
// warp tile 64x32 via 4x4 m16n8k16 tiles, 4 K-steps per chunk.
// BNK=0: B gmem [K,N] row-major -> smem [k-row][n] 272B stride, trans-ldmatrix.
// BNK=1: B gmem [N,K] row-major -> smem [n-row][k] 144B stride, ldmatrix.
// NOLOA=1: drop A-lo plane + its MMA term (for P in [0,1]).
#define LDA_B   144                  // A smem row stride bytes (64h + 8h pad)
#define LDB_B   272                  // B-trans smem row stride (128h + 8h pad)
#define APL     18432                // 128 * 144
#define BTPL    17408                // 64 * 272

template <int BNK, int NOLOA>
__global__ __launch_bounds__(256, 1)
void hmma_gemm(const float* __restrict__ A, int lda, long sA,
               const float* __restrict__ B, int ldb, long sB,
               float* __restrict__ C, int ldc, long sC,
               int K, float alpha)
{
    constexpr int ATOT   = (NOLOA ? 1 : 2) * APL;
    constexpr int BPLANE = BNK ? APL : BTPL;
    constexpr int STAGE  = ATOT + 2 * BPLANE;

    extern __shared__ char sm[];
    const uint32_t sbase = smem_u32(sm);

    const int tid = threadIdx.x;
    const int lane = tid & 31;
    const int wid = tid >> 5;

    const int bz = blockIdx.z;
    A += (long)bz * sA;
    B += (long)bz * sB;
    C += (long)bz * sC;
    const int row0 = blockIdx.y * 128;
    const int col0 = blockIdx.x * 128;

    const int mb = (wid >> 2) * 64;   // warp M offset
    const int nb = (wid & 3) * 32;    // warp N offset

    // fragment base addresses (per-lane)
    const uint32_t aFrag = sbase + (uint32_t)((mb + (lane & 15)) * LDA_B + (lane >> 4) * 16);
    const uint32_t bFrag = BNK
        ? sbase + ATOT +
          (uint32_t)((nb + (lane & 7) + ((lane >> 4) & 1) * 8) * LDA_B + ((lane >> 3) & 1) * 16)
        : sbase + ATOT +
          (uint32_t)(((lane & 7) + ((lane >> 3) & 1) * 8) * LDB_B + (nb + (lane >> 4) * 8) * 2);

    float acc[4][4][4];
    #pragma unroll
    for (int i = 0; i < 4; i++)
        #pragma unroll
        for (int j = 0; j < 4; j++)
            #pragma unroll
            for (int e = 0; e < 4; e++) acc[i][j][e] = 0.0f;

    const int nIter = K / 64;
    float4 aReg[8], bReg[8];

    // gmem loads for chunk k0 (A: 128x64 fp32; B: 64x128 or 128x64 fp32)
    auto ldg = [&](int k0) {
        #pragma unroll
        for (int j = 0; j < 8; j++) {
            const int f = j * 256 + tid;
            const int r = f >> 4, c = (f & 15) << 2;
            aReg[j] = *reinterpret_cast<const float4*>(
                A + (long)(row0 + r) * lda + k0 + c);
        }
        if (BNK) {
            #pragma unroll
            for (int j = 0; j < 8; j++) {
                const int f = j * 256 + tid;
                const int r = f >> 4, c = (f & 15) << 2;
                bReg[j] = *reinterpret_cast<const float4*>(
                    B + (long)(col0 + r) * ldb + k0 + c);
            }
        } else {
            #pragma unroll
            for (int j = 0; j < 8; j++) {
                const int f = j * 256 + tid;
                const int kr = f >> 5, n4 = (f & 31) << 2;
                bReg[j] = *reinterpret_cast<const float4*>(
                    B + (long)(k0 + kr) * ldb + col0 + n4);
            }
        }
    };
    // convert + store staged regs into stage st
    auto sts = [&](uint32_t st) {
        #pragma unroll
        for (int j = 0; j < 8; j++) {
            const int f = j * 256 + tid;
            const int r = f >> 4, c = (f & 15) << 2;
            uint32_t ad = sbase + st + (uint32_t)(r * LDA_B + c * 2);
            if (NOLOA) {
                uint32_t h[2];
                hi4(aReg[j], h);
                sts64(ad, h[0], h[1]);
            } else {
                uint32_t h[2], l[2];
                split4(aReg[j], h, l);
                sts64(ad, h[0], h[1]);
                sts64(ad + APL, l[0], l[1]);
            }
        }
        #pragma unroll
        for (int j = 0; j < 8; j++) {
            const int f = j * 256 + tid;
            uint32_t h[2], l[2];
            split4(bReg[j], h, l);
            uint32_t ad;
            if (BNK) {
                const int r = f >> 4, c = (f & 15) << 2;
                ad = sbase + st + ATOT + (uint32_t)(r * LDA_B + c * 2);
            } else {
                const int kr = f >> 5, n4 = (f & 31) << 2;
                ad = sbase + st + ATOT + (uint32_t)(kr * LDB_B + n4 * 2);
            }
            sts64(ad, h[0], h[1]);
            sts64(ad + BPLANE, l[0], l[1]);
        }
    };

    ldg(0);
    sts(0);
    __syncthreads();

    for (int kb = 0; kb < nIter; kb++) {
        if (kb + 1 < nIter) ldg((kb + 1) * 64);   // prefetch next chunk

        const uint32_t st = (uint32_t)(kb & 1) * STAGE;
        #pragma unroll
        for (int ks = 0; ks < 4; ks++) {
            uint32_t ah[4][4], al[4][4], bh[4][2], bl[4][2];
            #pragma unroll
            for (int i = 0; i < 4; i++) {
                uint32_t ad = aFrag + st + (uint32_t)(i * 16 * LDA_B + ks * 32);
                LDSM_X4(ah[i], ad);
                if (!NOLOA) LDSM_X4(al[i], ad + APL);
            }
            #pragma unroll
            for (int j2 = 0; j2 < 2; j2++) {
                if (BNK) {
                    uint32_t bd = bFrag + st + (uint32_t)(j2 * 16 * LDA_B + ks * 32);
                    LDSM_X4(bh[2 * j2], bd);
                    LDSM_X4(bl[2 * j2], bd + BPLANE);
                } else {
                    uint32_t bd = bFrag + st + (uint32_t)(ks * 16 * LDB_B + j2 * 32);
                    LDSM_X4_T(bh[2 * j2][0], bh[2 * j2][1], bh[2 * j2 + 1][0], bh[2 * j2 + 1][1], bd);
                    LDSM_X4_T(bl[2 * j2][0], bl[2 * j2][1], bl[2 * j2 + 1][0], bl[2 * j2 + 1][1],
                              bd + BPLANE);
                }
            }
            #pragma unroll
            for (int i = 0; i < 4; i++)
                #pragma unroll
                for (int j = 0; j < 4; j++) mma16816(acc[i][j], ah[i], bh[j]);
            #pragma unroll
            for (int i = 0; i < 4; i++)
                #pragma unroll
                for (int j = 0; j < 4; j++) mma16816(acc[i][j], ah[i], bl[j]);
            if (!NOLOA) {
                #pragma unroll
                for (int i = 0; i < 4; i++)
                    #pragma unroll
                    for (int j = 0; j < 4; j++) mma16816(acc[i][j], al[i], bh[j]);
            }
        }

        if (kb + 1 < nIter) sts((uint32_t)((kb + 1) & 1) * STAGE);
        __syncthreads();
    }

    // epilogue
    #pragma unroll
    for (int i = 0; i < 4; i++) {
        const int r = row0 + mb + i * 16 + (lane >> 2);
        #pragma unroll
        for (int j = 0; j < 4; j++) {
            const int c = col0 + nb + j * 8 + (lane & 3) * 2;
            float2 v0 = make_float2(acc[i][j][0] * alpha, acc[i][j][1] * alpha);
            float2 v1 = make_float2(acc[i][j][2] * alpha, acc[i][j][3] * alpha);
            *reinterpret_cast<float2*>(C + (long)r * ldc + c) = v0;
            *reinterpret_cast<float2*>(C + (long)(r + 8) * ldc + c) = v1;
        }
    }
}

// ---------------- softmax: one row (2048) per 256-thread block ----------------
__global__ __launch_bounds__(256)
void softmax_kernel(float* __restrict__ scores)
{
    __shared__ float red[8];
    const long row = blockIdx.x;
    float4* r4 = reinterpret_cast<float4*>(scores + row * (long)SEQ);
    const int tid = threadIdx.x;
    const int wid = tid >> 5, lane = tid & 31;

    float4 a = r4[tid];
    float4 b = r4[tid + 256];

    float m = fmaxf(fmaxf(fmaxf(a.x, a.y), fmaxf(a.z, a.w)),
                    fmaxf(fmaxf(b.x, b.y), fmaxf(b.z, b.w)));
    #pragma unroll
    for (int o = 16; o; o >>= 1) m = fmaxf(m, __shfl_xor_sync(0xffffffffu, m, o));
    if (lane == 0) red[wid] = m;
    __syncthreads();
    float rowmax = red[0];
    #pragma unroll
    for (int i = 1; i < 8; i++) rowmax = fmaxf(rowmax, red[i]);
    __syncthreads();

    a.x = __expf(a.x - rowmax); a.y = __expf(a.y - rowmax);
    a.z = __expf(a.z - rowmax); a.w = __expf(a.w - rowmax);
    b.x = __expf(b.x - rowmax); b.y = __expf(b.y - rowmax);
    b.z = __expf(b.z - rowmax); b.w = __expf(b.w - rowmax);

    float s = a.x + a.y + a.z + a.w + b.x + b.y + b.z + b.w;
    #pragma unroll
    for (int o = 16; o; o >>= 1) s += __shfl_xor_sync(0xffffffffu, s, o);
    if (lane == 0) red[wid] = s;
    __syncthreads();
    float tot = red[0];
    #pragma unroll
    for (int i = 1; i < 8; i++) tot += red[i];
    const float inv = 1.0f / tot;

    a.x *= inv; a.y *= inv; a.z *= inv; a.w *= inv;
    b.x *= inv; b.y *= inv; b.z *= inv; b.w *= inv;
    r4[tid] = a;
    r4[tid + 256] = b;
}

// ---------------- launch ----------------
extern "C" void kernel_launch(void* const* d_in, const int* in_sizes, int n_in,
                              void* d_out, int out_size)
{
    const float* hidden = (const float*)d_in[0];   // [4,2048,1024]
    const float* W      = (const float*)d_in[1];   // [1024,3072]
    float* out          = (float*)d_out;           // [4,2048,1024]

    float* qkv = nullptr; float* scores = nullptr;
    cudaGetSymbolAddress((void**)&qkv, g_qkv);
    cudaGetSymbolAddress((void**)&scores, g_scores);

    constexpr int SM1 = 2 * (2 * APL + 2 * BTPL);  // 143360  GEMM1 (BNK=0, 3-term)
    constexpr int SM2 = 2 * (2 * APL + 2 * APL);   // 147456  GEMM2 (BNK=1, 3-term)
    constexpr int SM3 = 2 * (1 * APL + 2 * BTPL);  // 106496  GEMM3 (BNK=0, 2-term)
    cudaFuncSetAttribute(hmma_gemm<0, 0>, cudaFuncAttributeMaxDynamicSharedMemorySize, SM1);
    cudaFuncSetAttribute(hmma_gemm<1, 0>, cudaFuncAttributeMaxDynamicSharedMemorySize, SM2);
    cudaFuncSetAttribute(hmma_gemm<0, 1>, cudaFuncAttributeMaxDynamicSharedMemorySize, SM3);

    // 1) qkv = hidden @ W   (M=8192, N=3072, K=1024), B=[K,N]
    hmma_gemm<0, 0><<<dim3(3 * EMB / 128, BS / 128, 1), 256, SM1>>>(
        hidden, EMB, 0,
        W, 3 * EMB, 0,
        qkv, 3 * EMB, 0,
        EMB, 1.0f);

    // 2) scores[b] = Q[b] @ K[b]^T * 1/32   (B = K-section rows, [N,K])
    hmma_gemm<1, 0><<<dim3(SEQ / 128, SEQ / 128, BATCH), 256, SM2>>>(
        qkv, 3 * EMB, (long)SEQ * 3 * EMB,
        qkv + EMB, 3 * EMB, (long)SEQ * 3 * EMB,
        scores, SEQ, (long)SEQ * SEQ,
        EMB, 1.0f / 32.0f);

    // 3) softmax rows (in place)
    softmax_kernel<<<BATCH * SEQ, 256>>>(scores);

    // 4) out[b] = P[b] @ V[b]   (M=2048, N=1024, K=2048), B=[K,N], 2-term P
    hmma_gemm<0, 1><<<dim3(EMB / 128, SEQ / 128, BATCH), 256, SM3>>>(
        scores, SEQ, (long)SEQ * SEQ,
        qkv + 2 * EMB, 3 * EMB, (long)SEQ * 3 * EMB,
        out, EMB, (long)SEQ * EMB,
        SEQ, 1.0f);
}